// round 16
// baseline (speedup 1.0000x reference)
#include <cuda_runtime.h>
#include <cuda_fp16.h>
#include <cstdint>

#define Bb 8
#define Tt 2048
#define Vv 1024
#define BM 128
#define BN 128
#define BK 64          // 64 fp16 = 128B per row
#define NTH 128
#define BUFB 32768     // A tile 16KB + B tile 16KB

// ---- scratch (static __device__ — no allocations allowed) ----
__device__ __half g_WkT[Vv * Vv];               // WkT[i][o] fp16
__device__ __half g_WqT[Vv * Vv];               // WqT[a][o] fp16
__device__ __half g_WvT[Vv * Vv];               // WvT[i][o] fp16
__device__ __half g_pv[Tt];
__device__ __half g_CT[Vv * Vv];                // CT[i][a] = (Wq^T Wk)[a][i]
__device__ __half g_Cg[(size_t)Bb * Vv * Tt];   // Cg[b][a][s'] = CT[idx[b][s']][a]
__device__ __half g_Gv[(size_t)Bb * Vv * Tt];   // Gv[b][o][s]  = WvT[idx[b][s]][o]
__device__ __half g_Ah[(size_t)Bb * Vv * Tt];   // Ah[b][a][s]

// ---------------- helpers ----------------
__device__ __forceinline__ uint32_t smem_u32(const void* p) {
    uint32_t a;
    asm("{ .reg .u64 t; cvta.to.shared.u64 t, %1; cvt.u32.u64 %0, t; }" : "=r"(a) : "l"(p));
    return a;
}
__device__ __forceinline__ void cpa16(uint32_t dst, const void* src) {
    asm volatile("cp.async.cg.shared.global [%0], [%1], 16;" :: "r"(dst), "l"(src) : "memory");
}
#define CP_COMMIT() asm volatile("cp.async.commit_group;" ::: "memory")
#define CP_WAIT1()  asm volatile("cp.async.wait_group 1;" ::: "memory")
#define CP_WAIT0()  asm volatile("cp.async.wait_group 0;" ::: "memory")

__device__ __forceinline__ void mma_f16(float* c, uint32_t a0, uint32_t a1,
                                        uint32_t a2, uint32_t a3,
                                        uint32_t b0, uint32_t b1) {
    asm volatile(
        "mma.sync.aligned.m16n8k16.row.col.f32.f16.f16.f32 "
        "{%0,%1,%2,%3}, {%4,%5,%6,%7}, {%8,%9}, {%0,%1,%2,%3};"
        : "+f"(c[0]), "+f"(c[1]), "+f"(c[2]), "+f"(c[3])
        : "r"(a0), "r"(a1), "r"(a2), "r"(a3), "r"(b0), "r"(b1));
}

// ---------------- MMA core: one BK=64 chunk, warp tile 64x64 ----------------
// smem tiles [row][k], 128B rows (64 fp16), 16B-granule XOR swizzle folded
// into ko[] (R12-proven addressing; word = fp16 pair).
__device__ __forceinline__ void mma_chunk(const char* Atp, const char* Btp,
                                          const uint32_t* ko, float acc[4][8][4]) {
#pragma unroll
    for (int j = 0; j < 4; j++) {          // 4 x k16 steps
        const char* alo = Atp + ko[j * 2 + 0];
        const char* ahi = Atp + ko[j * 2 + 1];
        const char* blo = Btp + ko[j * 2 + 0];
        const char* bhi = Btp + ko[j * 2 + 1];
        uint32_t a[4][4];
#pragma unroll
        for (int mf = 0; mf < 4; mf++) {
            a[mf][0] = *(const uint32_t*)(alo + mf * 2048);          // (row g,   k lo)
            a[mf][1] = *(const uint32_t*)(alo + mf * 2048 + 1024);   // (row g+8, k lo)
            a[mf][2] = *(const uint32_t*)(ahi + mf * 2048);          // (row g,   k hi)
            a[mf][3] = *(const uint32_t*)(ahi + mf * 2048 + 1024);   // (row g+8, k hi)
        }
#pragma unroll
        for (int nf = 0; nf < 8; nf++) {
            const uint32_t b0 = *(const uint32_t*)(blo + nf * 1024);
            const uint32_t b1 = *(const uint32_t*)(bhi + nf * 1024);
#pragma unroll
            for (int mf = 0; mf < 4; mf++)
                mma_f16(acc[mf][nf], a[mf][0], a[mf][1], a[mf][2], a[mf][3], b0, b1);
        }
    }
}

// 4 warps: wm = (wid&1)*64 (2 in m), wn = (wid>>1)*64 (2 in n)
#define GEMM_PROLOG() \
    extern __shared__ char dsm[]; \
    const int tid = threadIdx.x; \
    const int wid = tid >> 5, lane = tid & 31; \
    const int gid = lane >> 2, kq = lane & 3; \
    const int wm = (wid & 1) * 64, wn = (wid >> 1) * 64; \
    uint32_t ko[8]; \
    { const uint32_t xg = (uint32_t)(gid & 7) << 4; \
      _Pragma("unroll") for (int j = 0; j < 4; j++) \
      _Pragma("unroll") for (int h = 0; h < 2; h++) \
          ko[j * 2 + h] = ((uint32_t)((j * 8 + kq + h * 4) * 4)) ^ xg; } \
    const char* Abase = dsm + (wm + gid) * 128; \
    const char* Bbase = dsm + 16384 + (wn + gid) * 128; \
    const int rowF = tid; \
    char* fAp = dsm + rowF * 128; \
    char* fBp = fAp + 16384; \
    const uint32_t fA = smem_u32(fAp); \
    const uint32_t fB = fA + 16384; \
    const uint32_t fxg = (uint32_t)(rowF & 7) << 4; \
    (void)fBp; (void)fB; \
    float acc[4][8][4]; \
    _Pragma("unroll") for (int mf = 0; mf < 4; mf++) \
    _Pragma("unroll") for (int nf = 0; nf < 8; nf++) \
    _Pragma("unroll") for (int c = 0; c < 4; c++) acc[mf][nf][c] = 0.f;

// triple-buffered mainloop: fill 2 ahead, one sync per chunk (R7/R11/R12-proven)
#define GEMM_LOOP(nt, FILL) \
    FILL(0, 0u); CP_COMMIT(); \
    FILL(1, (uint32_t)BUFB); CP_COMMIT(); \
    { int p = 0; \
      for (int kt = 0; kt < (nt); kt++) { \
          if (kt + 1 < (nt)) CP_WAIT1(); else CP_WAIT0(); \
          __syncthreads(); \
          if (kt + 2 < (nt)) { \
              const int p2 = (p >= 1) ? p - 1 : 2; \
              FILL(kt + 2, (uint32_t)(p2 * BUFB)); CP_COMMIT(); \
          } \
          mma_chunk(Abase + p * BUFB, Bbase + p * BUFB, ko, acc); \
          p = (p == 2) ? 0 : p + 1; \
      } }

// fp32 epilogue (final output)
#define GEMM_EPI_F(dstptr, ldT, ROWBASE, COLBASE) \
    _Pragma("unroll") for (int mf = 0; mf < 4; mf++) \
    _Pragma("unroll") for (int h = 0; h < 2; h++) { \
        const int row_ = (ROWBASE) + wm + mf * 16 + gid + 8 * h; \
        float* orow_ = (dstptr) + (size_t)row_ * (ldT) + (COLBASE) + wn; \
        _Pragma("unroll") for (int nf = 0; nf < 8; nf++) \
            *(float2*)&orow_[nf * 8 + kq * 2] = \
                make_float2(acc[mf][nf][2 * h] + 0.001f, acc[mf][nf][2 * h + 1] + 0.001f); }

// fp16 epilogue (intermediate tensors consumed by later GEMMs)
#define GEMM_EPI_H(dstptr, ldT, ROWBASE, COLBASE) \
    _Pragma("unroll") for (int mf = 0; mf < 4; mf++) \
    _Pragma("unroll") for (int h = 0; h < 2; h++) { \
        const int row_ = (ROWBASE) + wm + mf * 16 + gid + 8 * h; \
        __half* orow_ = (dstptr) + (size_t)row_ * (ldT) + (COLBASE) + wn; \
        _Pragma("unroll") for (int nf = 0; nf < 8; nf++) \
            *reinterpret_cast<__half2*>(&orow_[nf * 8 + kq * 2]) = \
                __floats2half2_rn(acc[mf][nf][2 * h], acc[mf][nf][2 * h + 1]); }

// ---------------- prep kernels ----------------
__global__ void round_pv(const float* __restrict__ pv) {
    int i = blockIdx.x * 1024 + threadIdx.x;
    g_pv[i] = __float2half(pv[i]);
}

__global__ void transpose3(const float* __restrict__ Wk,
                           const float* __restrict__ Wq,
                           const float* __restrict__ Wv) {
    __shared__ float tile[32][33];
    const float* src;
    __half* dst;
    if (blockIdx.z == 0)      { src = Wk; dst = g_WkT; }
    else if (blockIdx.z == 1) { src = Wq; dst = g_WqT; }
    else                      { src = Wv; dst = g_WvT; }
    int x = blockIdx.x * 32 + threadIdx.x;
    int y = blockIdx.y * 32 + threadIdx.y;
#pragma unroll
    for (int i = 0; i < 32; i += 8)
        tile[threadIdx.y + i][threadIdx.x] = src[(size_t)(y + i) * Vv + x];
    __syncthreads();
    x = blockIdx.y * 32 + threadIdx.x;
    y = blockIdx.x * 32 + threadIdx.y;
#pragma unroll
    for (int i = 0; i < 32; i += 8)
        dst[(size_t)(y + i) * Vv + x] = __float2half(tile[threadIdx.x][threadIdx.y + i]);
}

// Gv[b][o][s] = WvT[idx[b][s]][o]   (z even)   (R12-proven version)
// Cg[b][a][s'] = CT[idx[b][s']][a]  (z odd)
__global__ void gather2(const int* __restrict__ idx) {
    __shared__ __half tile[32][33];
    const int z = blockIdx.z;
    const int b = z >> 1;
    const __half* WT = (z & 1) ? g_CT : g_WvT;
    __half* G        = (z & 1) ? g_Cg : g_Gv;
    const int o0 = blockIdx.x * 32, s0 = blockIdx.y * 32;
    const int tx = threadIdx.x, ty = threadIdx.y;
#pragma unroll
    for (int i = 0; i < 32; i += 8) {
        const int row = idx[b * Tt + s0 + ty + i];
        tile[ty + i][tx] = WT[(size_t)row * Vv + o0 + tx];
    }
    __syncthreads();
#pragma unroll
    for (int i = 0; i < 32; i += 8)
        G[((size_t)(b * Vv + o0 + ty + i)) * Tt + s0 + tx] = tile[tx][ty + i];
}

// ---------------------------------------------------------------------------
// Kernel A: CT[i][a] = sum_o WkT[i][o] * WqT[a][o]
// ---------------------------------------------------------------------------
__global__ __launch_bounds__(NTH, 2)
void kernel_CT() {
    const int i0 = blockIdx.y * BM;
    const int a0 = blockIdx.x * BN;
    GEMM_PROLOG();
    const __half* as = g_WkT + (size_t)(i0 + rowF) * Vv;
    const __half* bs = g_WqT + (size_t)(a0 + rowF) * Vv;
    auto fill = [&](int kt, uint32_t bo) {
        const int o0 = kt * BK;
#pragma unroll
        for (int ch = 0; ch < 8; ch++) {
            const uint32_t off = bo + (((uint32_t)(ch * 16)) ^ fxg);
            cpa16(fA + off, as + o0 + ch * 8);
            cpa16(fB + off, bs + o0 + ch * 8);
        }
    };
    const int nt = Vv / BK;   // 16
    GEMM_LOOP(nt, fill);
    GEMM_EPI_H(g_CT, Vv, i0, a0);
}

// ---------------------------------------------------------------------------
// Kernel B: Ah[b][a][s] = sum_{s'<=s} Cg[b][a][s'] * pv[s-s']   (causal Toeplitz)
// A = Cg (cp.async), B[s][s'] = pv[s-s'] generated + masked. Heavy-first.
// ---------------------------------------------------------------------------
__global__ __launch_bounds__(NTH, 2)
void kernel_Ah() {
    const int b  = blockIdx.z;
    const int a0 = blockIdx.y * BM;
    const int s0 = ((int)gridDim.x - 1 - (int)blockIdx.x) * BN;
    GEMM_PROLOG();
    const __half* as = g_Cg + ((size_t)(b * Vv + a0 + rowF)) * Tt;
    const int s = s0 + rowF;
    auto fill = [&](int kt, uint32_t bo) {
        const int sp0 = kt * BK;
#pragma unroll
        for (int ch = 0; ch < 8; ch++) {
            const uint32_t off = bo + (((uint32_t)(ch * 16)) ^ fxg);
            cpa16(fA + off, as + sp0 + ch * 8);
            __half tmp[8];
            const int base = sp0 + ch * 8;
#pragma unroll
            for (int jj = 0; jj < 8; jj++) {
                const int d = s - (base + jj);
                tmp[jj] = (d >= 0) ? g_pv[d] : __float2half(0.f);
            }
            *(uint4*)(fBp + off) = *(uint4*)tmp;
        }
    };
    const int nt = s0 / BK + BN / BK;
    GEMM_LOOP(nt, fill);
    GEMM_EPI_H(g_Ah + (size_t)b * Vv * Tt, Tt, a0, s0);
}

// ---------------------------------------------------------------------------
// Kernel C: out[b][t][o] = 1e-3 + sum_{s<=t} Ah[b][idx[b][t]][s] * Gv[b][o][s]
// Heavy-first on t.
// ---------------------------------------------------------------------------
__global__ __launch_bounds__(NTH, 2)
void kernel_out(const int* __restrict__ idx, float* __restrict__ out) {
    const int b  = blockIdx.z;
    const int t0 = ((int)gridDim.y - 1 - (int)blockIdx.y) * BM;
    const int n0 = blockIdx.x * BN;
    GEMM_PROLOG();
    const int t = t0 + rowF;
    const int ia = idx[b * Tt + t];
    const __half* as = g_Ah + ((size_t)(b * Vv + ia)) * Tt;
    const __half* bs = g_Gv + ((size_t)(b * Vv + n0 + rowF)) * Tt;
    const int nt = t0 / BK + BN / BK;
    auto fill = [&](int kt, uint32_t bo) {
        const int sp0 = kt * BK;
        if (kt >= nt - 2) {
            // diagonal region: manual masked A fill
#pragma unroll
            for (int ch = 0; ch < 8; ch++) {
                const uint32_t off = bo + (((uint32_t)(ch * 16)) ^ fxg);
                const int base = sp0 + ch * 8;
                __half tmp[8];
                *(uint4*)tmp = *(const uint4*)(as + base);
#pragma unroll
                for (int jj = 0; jj < 8; jj++)
                    if (base + jj > t) tmp[jj] = __float2half(0.f);
                *(uint4*)(fAp + off) = *(uint4*)tmp;
                cpa16(fB + off, bs + base);
            }
        } else {
#pragma unroll
            for (int ch = 0; ch < 8; ch++) {
                const uint32_t off = bo + (((uint32_t)(ch * 16)) ^ fxg);
                cpa16(fA + off, as + sp0 + ch * 8);
                cpa16(fB + off, bs + sp0 + ch * 8);
            }
        }
    };
    GEMM_LOOP(nt, fill);
    GEMM_EPI_F(out + (size_t)b * Tt * Vv, Vv, t0, n0);
}

// ---------------------------------------------------------------------------
extern "C" void kernel_launch(void* const* d_in, const int* in_sizes, int n_in,
                              void* d_out, int out_size) {
    const int*   idx = (const int*)d_in[0];
    const float* pv  = (const float*)d_in[1];
    const float* Wk  = (const float*)d_in[2];
    const float* Wq  = (const float*)d_in[3];
    const float* Wv  = (const float*)d_in[4];
    float* out = (float*)d_out;

    const int dynsmem = 3 * BUFB;  // 96 KB; 2 CTAs/SM -> 192 KB
    cudaFuncSetAttribute(kernel_CT,  cudaFuncAttributeMaxDynamicSharedMemorySize, dynsmem);
    cudaFuncSetAttribute(kernel_Ah,  cudaFuncAttributeMaxDynamicSharedMemorySize, dynsmem);
    cudaFuncSetAttribute(kernel_out, cudaFuncAttributeMaxDynamicSharedMemorySize, dynsmem);

    round_pv  <<<Tt / 1024, 1024>>>(pv);
    transpose3<<<dim3(Vv / 32, Vv / 32, 3), dim3(32, 8)>>>(Wk, Wq, Wv);
    kernel_CT <<<dim3(Vv / BN, Vv / BM, 1), NTH, dynsmem>>>();
    gather2   <<<dim3(Vv / 32, Tt / 32, Bb * 2), dim3(32, 8)>>>(idx);
    kernel_Ah <<<dim3(Tt / BN, Vv / BM, Bb), NTH, dynsmem>>>();
    kernel_out<<<dim3(Vv / BN, Tt / BM, Bb), NTH, dynsmem>>>(idx, out);
}

// round 17
// speedup vs baseline: 1.4536x; 1.4536x over previous
#include <cuda_runtime.h>
#include <cuda_fp16.h>
#include <cstdint>

#define Bb 8
#define Tt 2048
#define Vv 1024
#define BM 128
#define BN 128
#define BK 64          // 64 fp16 per k-chunk
#define NTH 256
#define BUFB 32768     // A tile 16KB + B tile 16KB
#define IDXOFF 98304   // idx cache after 3 buffers

// ---- scratch (static __device__ — no allocations allowed) ----
__device__ __half g_WkT[Vv * Vv];               // WkT[i][o]
__device__ __half g_WqT[Vv * Vv];               // WqT[a][o]
__device__ __half g_WvT[Vv * Vv];               // WvT[i][o]
__device__ __half g_pv[Tt];
__device__ __half g_CT[Vv * Vv];                // CT[i][a] = (Wq^T Wk)[a][i]
__device__ __half g_Ah[(size_t)Bb * Vv * Tt];   // Ah[b][a][s]

// ---------------- helpers ----------------
__device__ __forceinline__ uint32_t smem_u32(const void* p) {
    uint32_t a;
    asm("{ .reg .u64 t; cvta.to.shared.u64 t, %1; cvt.u32.u64 %0, t; }" : "=r"(a) : "l"(p));
    return a;
}
__device__ __forceinline__ void cpa16(uint32_t dst, const void* src) {
    asm volatile("cp.async.cg.shared.global [%0], [%1], 16;" :: "r"(dst), "l"(src) : "memory");
}
#define CP_COMMIT() asm volatile("cp.async.commit_group;" ::: "memory")
#define CP_WAIT1()  asm volatile("cp.async.wait_group 1;" ::: "memory")
#define CP_WAIT0()  asm volatile("cp.async.wait_group 0;" ::: "memory")

__device__ __forceinline__ void mma_f16(float* c, uint32_t a0, uint32_t a1,
                                        uint32_t a2, uint32_t a3,
                                        uint32_t b0, uint32_t b1) {
    asm volatile(
        "mma.sync.aligned.m16n8k16.row.col.f32.f16.f16.f32 "
        "{%0,%1,%2,%3}, {%4,%5,%6,%7}, {%8,%9}, {%0,%1,%2,%3};"
        : "+f"(c[0]), "+f"(c[1]), "+f"(c[2]), "+f"(c[3])
        : "r"(a0), "r"(a1), "r"(a2), "r"(a3), "r"(b0), "r"(b1));
}
__device__ __forceinline__ void ldsm4t(uint32_t& r0, uint32_t& r1, uint32_t& r2, uint32_t& r3,
                                       uint32_t addr) {
    asm volatile("ldmatrix.sync.aligned.m8n8.x4.trans.shared.b16 {%0,%1,%2,%3}, [%4];"
                 : "=r"(r0), "=r"(r1), "=r"(r2), "=r"(r3) : "r"(addr));
}

// ---------------- prep kernels ----------------
__global__ void round_pv(const float* __restrict__ pv) {
    int i = blockIdx.x * 1024 + threadIdx.x;
    g_pv[i] = __float2half(pv[i]);
}

__global__ void transpose3(const float* __restrict__ Wk,
                           const float* __restrict__ Wq,
                           const float* __restrict__ Wv) {
    __shared__ float tile[32][33];
    const float* src;
    __half* dst;
    if (blockIdx.z == 0)      { src = Wk; dst = g_WkT; }
    else if (blockIdx.z == 1) { src = Wq; dst = g_WqT; }
    else                      { src = Wv; dst = g_WvT; }
    int x = blockIdx.x * 32 + threadIdx.x;
    int y = blockIdx.y * 32 + threadIdx.y;
#pragma unroll
    for (int i = 0; i < 32; i += 8)
        tile[threadIdx.y + i][threadIdx.x] = src[(size_t)(y + i) * Vv + x];
    __syncthreads();
    x = blockIdx.y * 32 + threadIdx.x;
    y = blockIdx.x * 32 + threadIdx.y;
#pragma unroll
    for (int i = 0; i < 32; i += 8)
        dst[(size_t)(y + i) * Vv + x] = __float2half(tile[threadIdx.x][threadIdx.y + i]);
}

// ---------------------------------------------------------------------------
// Kernel A: CT[i][a] = sum_o WkT[i][o] * WqT[a][o]   (R12-exact scalar GEMM)
// ---------------------------------------------------------------------------
__global__ __launch_bounds__(NTH, 2)
void kernel_CT() {
    extern __shared__ char dsm[];
    const int i0 = blockIdx.y * BM;
    const int a0 = blockIdx.x * BN;
    const int tid = threadIdx.x;
    const int wid = tid >> 5, lane = tid & 31;
    const int gid = lane >> 2, kq = lane & 3;
    const int wm = (wid & 3) * 32, wn = (wid >> 2) * 64;
    uint32_t ko[8];
    { const uint32_t xg = (uint32_t)(gid & 7) << 4;
#pragma unroll
      for (int j = 0; j < 4; j++)
#pragma unroll
        for (int h = 0; h < 2; h++)
          ko[j * 2 + h] = ((uint32_t)((j * 8 + kq + h * 4) * 4)) ^ xg; }
    const char* Abase = dsm + (wm + gid) * 128;
    const char* Bfr   = dsm + 16384 + (wn + gid) * 128;
    const int rowF = tid >> 1, u0 = (tid & 1) * 4;
    const uint32_t fA = smem_u32(dsm) + (uint32_t)(rowF * 128);
    const uint32_t fB = fA + 16384u;
    const uint32_t fxg = (uint32_t)(rowF & 7) << 4;
    float acc[2][8][4];
#pragma unroll
    for (int mf = 0; mf < 2; mf++)
#pragma unroll
      for (int nf = 0; nf < 8; nf++)
#pragma unroll
        for (int c = 0; c < 4; c++) acc[mf][nf][c] = 0.f;

    const __half* as = g_WkT + (size_t)(i0 + rowF) * Vv;
    const __half* bs = g_WqT + (size_t)(a0 + rowF) * Vv;
    auto fill = [&](int kt, uint32_t bo) {
        const int o0 = kt * BK;
#pragma unroll
        for (int u = 0; u < 4; u++) {
            const int ch = u0 + u;
            const uint32_t off = bo + (((uint32_t)(ch * 16)) ^ fxg);
            cpa16(fA + off, as + o0 + ch * 8);
            cpa16(fB + off, bs + o0 + ch * 8);
        }
    };
    const int nt = Vv / BK;
    fill(0, 0u); CP_COMMIT();
    fill(1, (uint32_t)BUFB); CP_COMMIT();
    int p = 0;
    for (int kt = 0; kt < nt; kt++) {
        if (kt + 1 < nt) CP_WAIT1(); else CP_WAIT0();
        __syncthreads();
        if (kt + 2 < nt) {
            const int p2 = (p >= 1) ? p - 1 : 2;
            fill(kt + 2, (uint32_t)(p2 * BUFB)); CP_COMMIT();
        }
        const char* Atp = Abase + p * BUFB;
        const char* Btp = Bfr + p * BUFB;
#pragma unroll
        for (int j = 0; j < 4; j++) {
            const char* alo = Atp + ko[j * 2 + 0];
            const char* ahi = Atp + ko[j * 2 + 1];
            const char* blo = Btp + ko[j * 2 + 0];
            const char* bhi = Btp + ko[j * 2 + 1];
            uint32_t a[2][4];
#pragma unroll
            for (int mf = 0; mf < 2; mf++) {
                a[mf][0] = *(const uint32_t*)(alo + mf * 2048);
                a[mf][1] = *(const uint32_t*)(alo + mf * 2048 + 1024);
                a[mf][2] = *(const uint32_t*)(ahi + mf * 2048);
                a[mf][3] = *(const uint32_t*)(ahi + mf * 2048 + 1024);
            }
#pragma unroll
            for (int nf = 0; nf < 8; nf++) {
                const uint32_t b0 = *(const uint32_t*)(blo + nf * 1024);
                const uint32_t b1 = *(const uint32_t*)(bhi + nf * 1024);
#pragma unroll
                for (int mf = 0; mf < 2; mf++)
                    mma_f16(acc[mf][nf], a[mf][0], a[mf][1], a[mf][2], a[mf][3], b0, b1);
            }
        }
        p = (p == 2) ? 0 : p + 1;
    }
#pragma unroll
    for (int mf = 0; mf < 2; mf++)
#pragma unroll
      for (int h = 0; h < 2; h++) {
        const int row = i0 + wm + mf * 16 + gid + 8 * h;
        __half* orow = g_CT + (size_t)row * Vv + a0 + wn;
#pragma unroll
        for (int nf = 0; nf < 8; nf++)
            *reinterpret_cast<__half2*>(&orow[nf * 8 + kq * 2]) =
                __floats2half2_rn(acc[mf][nf][2 * h], acc[mf][nf][2 * h + 1]);
      }
}

// ---------------------------------------------------------------------------
// Kernel B: Ah[b][a][s] = sum_{s'<=s} CT[idx[b][s']][a] * pv[s-s']
// A gathered on the fly into [k=s'][m=a] smem (256B rows, g^=(k&7) swizzle),
// fragments via ldmatrix.x4.trans. B Toeplitz generated (R12 path). Heavy-first.
// ---------------------------------------------------------------------------
__global__ __launch_bounds__(NTH, 2)
void kernel_Ah(const int* __restrict__ idx) {
    extern __shared__ char dsm[];
    const int b  = blockIdx.z;
    const int a0 = blockIdx.y * BM;
    const int s0 = ((int)gridDim.x - 1 - (int)blockIdx.x) * BN;
    const int tid = threadIdx.x;
    const int wid = tid >> 5, lane = tid & 31;
    const int gid = lane >> 2, kq = lane & 3;
    const int wm = (wid & 3) * 32, wn = (wid >> 2) * 64;
    const int l7 = lane & 7;
    uint32_t ko[8];
    { const uint32_t xg = (uint32_t)(gid & 7) << 4;
#pragma unroll
      for (int j = 0; j < 4; j++)
#pragma unroll
        for (int h = 0; h < 2; h++)
          ko[j * 2 + h] = ((uint32_t)((j * 8 + kq + h * 4) * 4)) ^ xg; }
    const uint32_t sbase = smem_u32(dsm);
    // A trans fragment offsets: lanes 0-7: k0-7@m-lo, 8-15: k0-7@m-hi,
    // 16-23: k8-15@m-lo, 24-31: k8-15@m-hi  -> {a0,a1,a2,a3}
    uint32_t aOff[2];
    { const int aK = l7 + ((lane & 16) >> 1);     // +8 rows for lanes 16-31
      const int aG = (lane >> 3) & 1;             // m+8 granule for odd groups
#pragma unroll
      for (int mf = 0; mf < 2; mf++) {
        const int g = (wm >> 3) + mf * 2 + aG;
        aOff[mf] = (uint32_t)(aK * 256 + ((g ^ l7) << 4));
      } }
    const char* Bfr = dsm + 16384 + (wn + gid) * 128;

    int* sIdx = (int*)(dsm + IDXOFF);
    for (int i = tid; i < Tt; i += NTH) sIdx[i] = idx[b * Tt + i];
    __syncthreads();

    // fills
    const int fAk = tid >> 2, fAg0 = tid & 3;
    const uint32_t fAdst = sbase + (uint32_t)(fAk * 256);
    const int rowF = tid >> 1, u0 = (tid & 1) * 4;
    char* fBp = dsm + 16384 + rowF * 128;
    const uint32_t fxg = (uint32_t)(rowF & 7) << 4;
    const int s = s0 + rowF;

    float acc[2][8][4];
#pragma unroll
    for (int mf = 0; mf < 2; mf++)
#pragma unroll
      for (int nf = 0; nf < 8; nf++)
#pragma unroll
        for (int c = 0; c < 4; c++) acc[mf][nf][c] = 0.f;

    auto fill = [&](int kt, uint32_t bo) {
        const int sp0 = kt * BK;
        const int iv = sIdx[sp0 + fAk];
        const __half* srcA = g_CT + (size_t)iv * Vv + a0;
        const uint32_t fswz = (uint32_t)((fAk & 7) << 4);
#pragma unroll
        for (int u = 0; u < 4; u++) {
            const int g = fAg0 + 4 * u;
            cpa16(fAdst + bo + (((uint32_t)(g << 4)) ^ fswz), srcA + g * 8);
        }
#pragma unroll
        for (int u = 0; u < 4; u++) {
            const int ch = u0 + u;
            const uint32_t off = bo + (((uint32_t)(ch * 16)) ^ fxg);
            __half tmp[8];
            const int base = sp0 + ch * 8;
#pragma unroll
            for (int jj = 0; jj < 8; jj++) {
                const int d = s - (base + jj);
                tmp[jj] = (d >= 0) ? g_pv[d] : __float2half(0.f);
            }
            *(uint4*)(fBp + off) = *(uint4*)tmp;
        }
    };

    const int nt = s0 / BK + BN / BK;
    fill(0, 0u); CP_COMMIT();
    fill(1, (uint32_t)BUFB); CP_COMMIT();
    int p = 0;
    for (int kt = 0; kt < nt; kt++) {
        if (kt + 1 < nt) CP_WAIT1(); else CP_WAIT0();
        __syncthreads();
        if (kt + 2 < nt) {
            const int p2 = (p >= 1) ? p - 1 : 2;
            fill(kt + 2, (uint32_t)(p2 * BUFB)); CP_COMMIT();
        }
        const uint32_t tA = sbase + (uint32_t)(p * BUFB);
        const char* Btp = Bfr + p * BUFB;
#pragma unroll
        for (int j = 0; j < 4; j++) {
            uint32_t a[2][4];
#pragma unroll
            for (int mf = 0; mf < 2; mf++)
                ldsm4t(a[mf][0], a[mf][1], a[mf][2], a[mf][3],
                       tA + (uint32_t)(j * 4096) + aOff[mf]);
            const char* blo = Btp + ko[j * 2 + 0];
            const char* bhi = Btp + ko[j * 2 + 1];
#pragma unroll
            for (int nf = 0; nf < 8; nf++) {
                const uint32_t b0 = *(const uint32_t*)(blo + nf * 1024);
                const uint32_t b1 = *(const uint32_t*)(bhi + nf * 1024);
#pragma unroll
                for (int mf = 0; mf < 2; mf++)
                    mma_f16(acc[mf][nf], a[mf][0], a[mf][1], a[mf][2], a[mf][3], b0, b1);
            }
        }
        p = (p == 2) ? 0 : p + 1;
    }
#pragma unroll
    for (int mf = 0; mf < 2; mf++)
#pragma unroll
      for (int h = 0; h < 2; h++) {
        const int row = a0 + wm + mf * 16 + gid + 8 * h;
        __half* orow = g_Ah + ((size_t)(b * Vv + row)) * Tt + s0 + wn;
#pragma unroll
        for (int nf = 0; nf < 8; nf++)
            *reinterpret_cast<__half2*>(&orow[nf * 8 + kq * 2]) =
                __floats2half2_rn(acc[mf][nf][2 * h], acc[mf][nf][2 * h + 1]);
      }
}

// ---------------------------------------------------------------------------
// Kernel C: out[b][t][o] = 1e-3 + sum_{s<=t} Ah[b][idx[b][t]][s] * WvT[idx[b][s]][o]
// A = gathered Ah rows, [m=t][k=s] scalar path (R12). B gathered on the fly into
// [k=s][n=o] smem, fragments via ldmatrix.x4.trans. Heavy-first on t.
// ---------------------------------------------------------------------------
__global__ __launch_bounds__(NTH, 2)
void kernel_out(const int* __restrict__ idx, float* __restrict__ out) {
    extern __shared__ char dsm[];
    const int b  = blockIdx.z;
    const int t0 = ((int)gridDim.y - 1 - (int)blockIdx.y) * BM;
    const int n0 = blockIdx.x * BN;
    const int tid = threadIdx.x;
    const int wid = tid >> 5, lane = tid & 31;
    const int gid = lane >> 2, kq = lane & 3;
    const int wm = (wid & 3) * 32, wn = (wid >> 2) * 64;
    const int l7 = lane & 7;
    uint32_t ko[8];
    { const uint32_t xg = (uint32_t)(gid & 7) << 4;
#pragma unroll
      for (int j = 0; j < 4; j++)
#pragma unroll
        for (int h = 0; h < 2; h++)
          ko[j * 2 + h] = ((uint32_t)((j * 8 + kq + h * 4) * 4)) ^ xg; }
    const uint32_t sbase = smem_u32(dsm);
    const char* Abase = dsm + (wm + gid) * 128;
    // B trans fragment offsets: lanes 0-7: k0-7@n(nf), 8-15: k8-15@n(nf),
    // 16-23: k0-7@n(nf+1), 24-31: k8-15@n(nf+1) -> {b0,b1,b0',b1'}
    uint32_t bOff[4];
    { const int bK = l7 + ((lane >> 3) & 1) * 8;
      const int bGl = lane >> 4;
#pragma unroll
      for (int nfp = 0; nfp < 4; nfp++) {
        const int g = (wn >> 3) + nfp * 2 + bGl;
        bOff[nfp] = (uint32_t)(bK * 256 + ((g ^ l7) << 4));
      } }

    int* sIdx = (int*)(dsm + IDXOFF);
    for (int i = tid; i < Tt; i += NTH) sIdx[i] = idx[b * Tt + i];
    __syncthreads();

    // A fill (R12 path, [m=t][k=s] 128B rows)
    const int rowF = tid >> 1, u0 = (tid & 1) * 4;
    char* fAp = dsm + rowF * 128;
    const uint32_t fA = smem_u32(fAp);
    const uint32_t fxg = (uint32_t)(rowF & 7) << 4;
    const int t = t0 + rowF;
    const int ia = sIdx[t];
    const __half* as = g_Ah + ((size_t)(b * Vv + ia)) * Tt;
    // B fill (gathered, [k=s][n=o] 256B rows)
    const int fBk = tid >> 2, fBg0 = tid & 3;
    const uint32_t fBdst = sbase + 16384u + (uint32_t)(fBk * 256);
    const uint32_t fBswz = (uint32_t)((fBk & 7) << 4);

    float acc[2][8][4];
#pragma unroll
    for (int mf = 0; mf < 2; mf++)
#pragma unroll
      for (int nf = 0; nf < 8; nf++)
#pragma unroll
        for (int c = 0; c < 4; c++) acc[mf][nf][c] = 0.f;

    const int nt = t0 / BK + BM / BK;
    auto fill = [&](int kt, uint32_t bo) {
        const int sp0 = kt * BK;
        if (kt >= nt - 2) {
#pragma unroll
            for (int u = 0; u < 4; u++) {
                const int ch = u0 + u;
                const uint32_t off = bo + (((uint32_t)(ch * 16)) ^ fxg);
                const int base = sp0 + ch * 8;
                __half tmp[8];
                *(uint4*)tmp = *(const uint4*)(as + base);
#pragma unroll
                for (int jj = 0; jj < 8; jj++)
                    if (base + jj > t) tmp[jj] = __float2half(0.f);
                *(uint4*)(fAp + off) = *(uint4*)tmp;
            }
        } else {
#pragma unroll
            for (int u = 0; u < 4; u++) {
                const int ch = u0 + u;
                const uint32_t off = bo + (((uint32_t)(ch * 16)) ^ fxg);
                cpa16(fA + off, as + sp0 + ch * 8);
            }
        }
        const int iv = sIdx[sp0 + fBk];
        const __half* srcB = g_WvT + (size_t)iv * Vv + n0;
#pragma unroll
        for (int u = 0; u < 4; u++) {
            const int g = fBg0 + 4 * u;
            cpa16(fBdst + bo + (((uint32_t)(g << 4)) ^ fBswz), srcB + g * 8);
        }
    };

    fill(0, 0u); CP_COMMIT();
    fill(1, (uint32_t)BUFB); CP_COMMIT();
    int p = 0;
    for (int kt = 0; kt < nt; kt++) {
        if (kt + 1 < nt) CP_WAIT1(); else CP_WAIT0();
        __syncthreads();
        if (kt + 2 < nt) {
            const int p2 = (p >= 1) ? p - 1 : 2;
            fill(kt + 2, (uint32_t)(p2 * BUFB)); CP_COMMIT();
        }
        const char* Atp = Abase + p * BUFB;
        const uint32_t tB = sbase + (uint32_t)(p * BUFB) + 16384u;
#pragma unroll
        for (int j = 0; j < 4; j++) {
            const char* alo = Atp + ko[j * 2 + 0];
            const char* ahi = Atp + ko[j * 2 + 1];
            uint32_t a[2][4];
#pragma unroll
            for (int mf = 0; mf < 2; mf++) {
                a[mf][0] = *(const uint32_t*)(alo + mf * 2048);
                a[mf][1] = *(const uint32_t*)(alo + mf * 2048 + 1024);
                a[mf][2] = *(const uint32_t*)(ahi + mf * 2048);
                a[mf][3] = *(const uint32_t*)(ahi + mf * 2048 + 1024);
            }
#pragma unroll
            for (int nfp = 0; nfp < 4; nfp++) {
                uint32_t b0a, b1a, b0b, b1b;
                ldsm4t(b0a, b1a, b0b, b1b, tB + (uint32_t)(j * 4096) + bOff[nfp]);
#pragma unroll
                for (int mf = 0; mf < 2; mf++) {
                    mma_f16(acc[mf][nfp * 2],     a[mf][0], a[mf][1], a[mf][2], a[mf][3], b0a, b1a);
                    mma_f16(acc[mf][nfp * 2 + 1], a[mf][0], a[mf][1], a[mf][2], a[mf][3], b0b, b1b);
                }
            }
        }
        p = (p == 2) ? 0 : p + 1;
    }
#pragma unroll
    for (int mf = 0; mf < 2; mf++)
#pragma unroll
      for (int h = 0; h < 2; h++) {
        const int row = t0 + wm + mf * 16 + gid + 8 * h;
        float* orow = out + ((size_t)(b * Tt + row)) * Vv + n0 + wn;
#pragma unroll
        for (int nf = 0; nf < 8; nf++)
            *(float2*)&orow[nf * 8 + kq * 2] =
                make_float2(acc[mf][nf][2 * h] + 0.001f, acc[mf][nf][2 * h + 1] + 0.001f);
      }
}

// ---------------------------------------------------------------------------
extern "C" void kernel_launch(void* const* d_in, const int* in_sizes, int n_in,
                              void* d_out, int out_size) {
    const int*   idx = (const int*)d_in[0];
    const float* pv  = (const float*)d_in[1];
    const float* Wk  = (const float*)d_in[2];
    const float* Wq  = (const float*)d_in[3];
    const float* Wv  = (const float*)d_in[4];
    float* out = (float*)d_out;

    const int smemCT = 3 * BUFB;            // 96 KB
    const int smemG  = 3 * BUFB + 8192;     // +8 KB idx cache = 104 KB
    cudaFuncSetAttribute(kernel_CT,  cudaFuncAttributeMaxDynamicSharedMemorySize, smemCT);
    cudaFuncSetAttribute(kernel_Ah,  cudaFuncAttributeMaxDynamicSharedMemorySize, smemG);
    cudaFuncSetAttribute(kernel_out, cudaFuncAttributeMaxDynamicSharedMemorySize, smemG);

    round_pv  <<<Tt / 1024, 1024>>>(pv);
    transpose3<<<dim3(Vv / 32, Vv / 32, 3), dim3(32, 8)>>>(Wk, Wq, Wv);
    kernel_CT <<<dim3(Vv / BN, Vv / BM, 1), NTH, smemCT>>>();
    kernel_Ah <<<dim3(Tt / BN, Vv / BM, Bb), NTH, smemG>>>(idx);
    kernel_out<<<dim3(Vv / BN, Tt / BM, Bb), NTH, smemG>>>(idx, out);
}